// round 4
// baseline (speedup 1.0000x reference)
#include <cuda_runtime.h>
#include <cstdint>

// Problem constants
#define BATCH 16
#define HDIM  1024
#define WDIM  1024
#define HW    (HDIM * WDIM)          // 1<<20
#define NPIX  ((long long)BATCH * HW) // 16777216

// Tile config
#define TX 128
#define TY 32
#define HALO 5
#define PITCH 144                    // (TX + 2*HALO)=138 padded to mult of 16
#define TROWS (TY + 2*HALO)          // 42

// Global accumulators: A0, B0, A1, B1, E
__device__ double g_acc[5];

__global__ void zero_acc_kernel() {
    if (threadIdx.x < 5) g_acc[threadIdx.x] = 0.0;
}

__device__ __forceinline__ unsigned dp4a_u(unsigned a, unsigned b, unsigned c) {
    return __dp4a(a, b, c);
}

__global__ __launch_bounds__(256, 8)
void fused_loss_kernel(const float* __restrict__ s0,
                       const float* __restrict__ s1,
                       const int*   __restrict__ tgt) {
    __shared__ __align__(16) unsigned char s_t[TROWS * PITCH];  // target tile + halo (u8)
    __shared__ unsigned char s_h[TROWS * TX];                   // horizontal 11-sums (u8, <=11)
    __shared__ float wred[8][5];

    const int tid = threadIdx.x;
    const int bx = blockIdx.x, by = blockIdx.y, b = blockIdx.z;
    const int gx0 = bx * TX - HALO;
    const int gy0 = by * TY - HALO;

    // ---- Phase 1: load target tile (with zero-padded halo) into u8 smem ----
    const int* tb = tgt + (size_t)b * HW;
    for (int i = tid; i < TROWS * PITCH; i += 256) {
        const int r = i / PITCH;
        const int c = i - r * PITCH;
        int v = 0;
        const int gy = gy0 + r;
        const int gx = gx0 + c;
        if (c < TX + 2*HALO && (unsigned)gy < HDIM && (unsigned)gx < WDIM)
            v = __ldg(tb + gy * WDIM + gx);
        s_t[i] = (unsigned char)v;
    }
    __syncthreads();

    // ---- Phase 2: horizontal 11-sum via masked dp4a (4 word loads / output) ----
    const unsigned ones = 0x01010101u;
    for (int i = tid; i < TROWS * TX; i += 256) {
        const int r = i >> 7;          // TX == 128
        const int x = i & 127;
        const int base = r * PITCH + x;          // PITCH % 4 == 0 -> o = x&3
        const int o = base & 3;
        const unsigned* w = (const unsigned*)(s_t + (base & ~3));
        // window = bytes [base, base+10]
        const unsigned maskLo = ones << (8 * o);
        const unsigned mask2  = (o <= 1) ? (ones >> (8 * (1 - o))) : ones;
        const unsigned mask3  = (o >= 2) ? (ones >> (8 * (5 - o))) : 0u;
        unsigned s = dp4a_u(w[0], maskLo, 0u);
        s = dp4a_u(w[1], ones,  s);
        s = dp4a_u(w[2], mask2, s);
        s = dp4a_u(w[3], mask3, s);
        s_h[i] = (unsigned char)s;     // <= 11
    }
    __syncthreads();

    // ---- Phase 3: vertical sliding 11-sum + fused loss ----
    const int x    = tid & 127;        // column within tile (lanes consecutive -> coalesced)
    const int half = tid >> 7;         // 0 or 1
    const int y0   = half * 16;

    int box = 0;
    #pragma unroll
    for (int r = 0; r < 11; r++) box += (int)s_h[(y0 + r) * TX + x];

    const int gx = bx * TX + x;
    const size_t rowBase = (size_t)(by * TY) * WDIM + gx;
    const float* p00 = s0 + (size_t)(2 * b) * HW + rowBase;
    const float* p01 = p00 + HW;
    const float* p10 = s1 + (size_t)(2 * b) * HW + rowBase;
    const float* p11 = p10 + HW;

    float A0 = 0.f, B0 = 0.f, A1 = 0.f, B1 = 0.f;
    int E = 0;

    #pragma unroll 4
    for (int j = 0; j < 16; j++) {
        const int y = y0 + j;
        if (j) box += (int)s_h[(y + 10) * TX + x] - (int)s_h[(y - 1) * TX + x];
        const int t = (int)s_t[(y + HALO) * PITCH + (x + HALO)];
        const bool edge = (box != 121 * t);

        const size_t off = (size_t)y * WDIM;
        const float a0 = __ldg(p00 + off);
        const float c0 = __ldg(p01 + off);
        const float a1 = __ldg(p10 + off);
        const float c1 = __ldg(p11 + off);

        // log-softmax for C=2: lse = max + log(1 + exp(-|d|))
        const float d0   = a0 - c0;
        const float lse0 = fmaxf(a0, c0) + __logf(1.0f + __expf(-fabsf(d0)));
        const float lpa0 = a0 - lse0, lpb0 = c0 - lse0;
        const float lpt0 = t ? lpb0 : lpa0;

        const float d1   = a1 - c1;
        const float lse1 = fmaxf(a1, c1) + __logf(1.0f + __expf(-fabsf(d1)));
        const float lpa1 = a1 - lse1, lpb1 = c1 - lse1;
        const float lpt1 = t ? lpb1 : lpa1;

        A0 += lpt0;
        A1 += lpt1;
        if (edge) {
            B0 += (lpa0 + lpb0) - 1.5f * lpt0;
            B1 += (lpa1 + lpb1) - 1.5f * lpt1;
            E++;
        }
    }

    // ---- Block reduction -> 5 double atomics ----
    float vals[5] = {A0, B0, A1, B1, (float)E};
    #pragma unroll
    for (int k = 0; k < 5; k++) {
        #pragma unroll
        for (int off = 16; off; off >>= 1)
            vals[k] += __shfl_down_sync(0xFFFFFFFFu, vals[k], off);
    }
    const int warp = tid >> 5, lane = tid & 31;
    if (lane == 0) {
        #pragma unroll
        for (int k = 0; k < 5; k++) wred[warp][k] = vals[k];
    }
    __syncthreads();
    if (tid == 0) {
        double acc[5] = {0, 0, 0, 0, 0};
        #pragma unroll
        for (int w = 0; w < 8; w++)
            #pragma unroll
            for (int k = 0; k < 5; k++) acc[k] += (double)wred[w][k];
        #pragma unroll
        for (int k = 0; k < 5; k++) atomicAdd(&g_acc[k], acc[k]);
    }
}

__global__ void finalize_kernel(float* __restrict__ out) {
    const double N = (double)NPIX;
    const double E = g_acc[4];
    double alpha = E / N;
    if (alpha > 0.2) alpha = 0.2;
    const double l0 = -(g_acc[0] + alpha * g_acc[1]) / N;
    const double l1 = -(g_acc[2] + alpha * g_acc[3]) / N;
    out[0] = (float)(l0 + 0.5 * l1);
}

extern "C" void kernel_launch(void* const* d_in, const int* in_sizes, int n_in,
                              void* d_out, int out_size) {
    const float* s0 = (const float*)d_in[0];
    const float* s1 = (const float*)d_in[1];
    const int*   tg = (const int*)d_in[2];

    zero_acc_kernel<<<1, 32>>>();
    dim3 grid(WDIM / TX, HDIM / TY, BATCH);   // (8, 32, 16) = 4096 blocks
    fused_loss_kernel<<<grid, 256>>>(s0, s1, tg);
    finalize_kernel<<<1, 1>>>((float*)d_out);
}